// round 1
// baseline (speedup 1.0000x reference)
#include <cuda_runtime.h>
#include <math.h>

// Problem constants (shapes fixed by the dataset)
#define MAXN 10000
#define MAXE 320000

// Scratch (allocation-free rule: __device__ globals)
__device__ float g_y[MAXN * 256];    // per-node: y0[64], then y1 m-major: [64 + m*64 + u]
__device__ float g_agg[MAXN * 512];  // per-node aggregated edge features (reference concat layout)

// ---------------------------------------------------------------------------
// Zero the aggregation buffer (vectorized)
__global__ void zero_agg_kernel(int n) {
    int i = blockIdx.x * blockDim.x + threadIdx.x;
    int total = n * 128;  // n*512 floats / 4
    if (i < total) reinterpret_cast<float4*>(g_agg)[i] = make_float4(0.f, 0.f, 0.f, 0.f);
}

// ---------------------------------------------------------------------------
// Node pre: y0 = x0 @ W_lin1_0 / 8 ; y1[:,v,m] = sum_u x1[:,u,m] W_lin1_1[u,v] / 8
// One block (64 threads) per node; thread = output channel v.
__global__ void node_pre_kernel(const float* __restrict__ nf,
                                const float* __restrict__ Wl0,
                                const float* __restrict__ Wl1,
                                int n) {
    int node = blockIdx.x;
    if (node >= n) return;
    int v = threadIdx.x;  // 0..63

    __shared__ float xs[256];
    const float* row = nf + (size_t)node * 256;
    for (int i = v; i < 256; i += 64) xs[i] = row[i];
    __syncthreads();

    float y0 = 0.f, y1a = 0.f, y1b = 0.f, y1c = 0.f;
    #pragma unroll 8
    for (int u = 0; u < 64; ++u) {
        float w0 = __ldg(Wl0 + u * 64 + v);
        float w1 = __ldg(Wl1 + u * 64 + v);
        y0  += xs[u] * w0;
        y1a += xs[64 + u * 3 + 0] * w1;
        y1b += xs[64 + u * 3 + 1] * w1;
        y1c += xs[64 + u * 3 + 2] * w1;
    }
    const float s = 0.125f;  // 1/sqrt(C)
    float* out = g_y + (size_t)node * 256;
    out[v]            = y0  * s;
    out[64  + v]      = y1a * s;   // m=0, m-major
    out[128 + v]      = y1b * s;   // m=1
    out[192 + v]      = y1c * s;   // m=2
}

// ---------------------------------------------------------------------------
// Edge kernel: per-edge MLP + gather y[src] + compute 512-dim feature + scatter-add.
// 256 threads = 4 edges x 64 threads; thread = channel u.
__global__ void edge_kernel(const float* __restrict__ eattr,
                            const float* __restrict__ eemb,
                            const int*   __restrict__ eidx,
                            const float* __restrict__ Wfc1,
                            const float* __restrict__ Wfc2,
                            int E) {
    __shared__ float sW1[64];        // 8x8
    __shared__ float sW2[8 * 256];   // 8x256
    int tid = threadIdx.x;
    for (int i = tid; i < 64;   i += 256) sW1[i] = Wfc1[i];
    for (int i = tid; i < 2048; i += 256) sW2[i] = Wfc2[i];
    __syncthreads();

    int e = blockIdx.x * 4 + (tid >> 6);
    if (e >= E) return;
    int u = tid & 63;

    // h = softplus(emb @ W_fc1 / sqrt(8)) - log2   (computed redundantly per thread: 64 MACs)
    float emb[8];
    #pragma unroll
    for (int j = 0; j < 8; ++j) emb[j] = __ldg(eemb + (size_t)e * 8 + j);

    const float INV_SQRT8 = 0.35355339059327373f;
    float h[8];
    #pragma unroll
    for (int j = 0; j < 8; ++j) {
        float z = 0.f;
        #pragma unroll
        for (int k = 0; k < 8; ++k) z += emb[k] * sW1[k * 8 + j];
        z *= INV_SQRT8;
        float sp = (z > 80.f) ? z : log1pf(__expf(z));
        h[j] = sp - 0.6931471805599453f;
    }

    // w = h @ W_fc2 / sqrt(8); this thread needs columns u, 64+u, 128+u, 192+u
    float w1 = 0.f, w2 = 0.f, w3 = 0.f, w4 = 0.f;
    #pragma unroll
    for (int j = 0; j < 8; ++j) {
        const float* r = sW2 + j * 256;
        float hj = h[j];
        w1 += hj * r[u];
        w2 += hj * r[64 + u];
        w3 += hj * r[128 + u];
        w4 += hj * r[192 + u];
    }
    w1 *= INV_SQRT8; w2 *= INV_SQRT8; w3 *= INV_SQRT8; w4 *= INV_SQRT8;

    int dst = __ldg(eidx + e);
    int src = __ldg(eidx + E + e);
    float sh0  = __ldg(eattr + (size_t)e * 4 + 0);
    float sh1x = __ldg(eattr + (size_t)e * 4 + 1);
    float sh1y = __ldg(eattr + (size_t)e * 4 + 2);
    float sh1z = __ldg(eattr + (size_t)e * 4 + 3);

    const float* ysrc = g_y + (size_t)src * 256;   // L2-resident (10 MB)
    float xs0 = ysrc[u];
    float x1x = ysrc[64  + u];
    float x1y = ysrc[128 + u];
    float x1z = ysrc[192 + u];

    float ms0  = w1 * xs0 * sh0;
    float dotv = x1x * sh1x + x1y * sh1y + x1z * sh1z;
    float ms1  = w4 * dotv * 0.5773502691896258f;  // 1/sqrt(3)
    float a2   = w2 * xs0;
    float a3   = w3 * sh0;

    float* arow = g_agg + (size_t)dst * 512;
    atomicAdd(arow + u,       ms0);
    atomicAdd(arow + 64 + u,  ms1);
    atomicAdd(arow + 128 + 3 * u + 0, a2 * sh1x);
    atomicAdd(arow + 128 + 3 * u + 1, a2 * sh1y);
    atomicAdd(arow + 128 + 3 * u + 2, a2 * sh1z);
    atomicAdd(arow + 320 + 3 * u + 0, a3 * x1x);
    atomicAdd(arow + 320 + 3 * u + 1, a3 * x1y);
    atomicAdd(arow + 320 + 3 * u + 2, a3 * x1z);
}

// ---------------------------------------------------------------------------
// Node post: o0 = s @ W_lin2_0 /64 + sc0 ; o1 = v·W_lin2_1 /64 + sc1
// (1/64 = 1/sqrt(AVG_NEIGH) * 1/sqrt(2C)); sc terms scaled 1/16.
// One block (256 threads) per node: t<64 -> o0[v]; t>=64 -> o1[v,m] (m = (t-64)>>6).
__global__ void node_post_kernel(const float* __restrict__ nf,
                                 const float* __restrict__ attrs,
                                 const float* __restrict__ Wl20,
                                 const float* __restrict__ Wl21,
                                 const float* __restrict__ Wsc0,
                                 const float* __restrict__ Wsc1,
                                 float* __restrict__ out,
                                 int n) {
    int node = blockIdx.x;
    if (node >= n) return;
    int t = threadIdx.x;

    __shared__ float sagg[512];
    __shared__ float sx[256];
    __shared__ float sa[4];
    const float* arow = nf; // placate compiler; real ptr below
    arow = g_agg + (size_t)node * 512;
    for (int i = t; i < 512; i += 256) sagg[i] = arow[i];
    sx[t] = nf[(size_t)node * 256 + t];
    if (t < 4) sa[t] = attrs[(size_t)node * 4 + t];
    __syncthreads();

    const float LIN2S = 0.015625f;  // 1/(sqrt(32)*sqrt(128)) = 1/64
    const float SCN   = 0.0625f;    // 1/sqrt(C*A) = 1/16

    if (t < 64) {
        int v = t;
        float acc = 0.f;
        #pragma unroll 8
        for (int k = 0; k < 128; ++k) acc += sagg[k] * __ldg(Wl20 + k * 64 + v);
        acc *= LIN2S;
        float sc = 0.f;
        for (int u = 0; u < 64; ++u) {
            const float* wrow = Wsc0 + u * 256;  // W_sc0[u, a, v]
            float tsum = 0.f;
            #pragma unroll
            for (int a = 0; a < 4; ++a) tsum += sa[a] * __ldg(wrow + a * 64 + v);
            sc += sx[u] * tsum;
        }
        out[(size_t)node * 256 + v] = acc + sc * SCN;
    } else {
        int m = (t - 64) >> 6;
        int v = (t - 64) & 63;
        float acc = 0.f;
        #pragma unroll 8
        for (int uu = 0; uu < 128; ++uu) acc += sagg[128 + uu * 3 + m] * __ldg(Wl21 + uu * 64 + v);
        acc *= LIN2S;
        float sc = 0.f;
        for (int u = 0; u < 64; ++u) {
            const float* wrow = Wsc1 + u * 256;  // W_sc1[u, a, v]
            float tsum = 0.f;
            #pragma unroll
            for (int a = 0; a < 4; ++a) tsum += sa[a] * __ldg(wrow + a * 64 + v);
            sc += sx[64 + u * 3 + m] * tsum;     // x1[n,u,m]
        }
        out[(size_t)node * 256 + 64 + v * 3 + m] = acc + sc * SCN;
    }
}

// ---------------------------------------------------------------------------
extern "C" void kernel_launch(void* const* d_in, const int* in_sizes, int n_in,
                              void* d_out, int out_size) {
    const float* nf    = (const float*)d_in[0];   // node_features (N, 256)
    const float* attrs = (const float*)d_in[1];   // node_attrs    (N, 4)
    const float* ea    = (const float*)d_in[2];   // edge_attrs    (E, 4)
    const float* ee    = (const float*)d_in[3];   // edge_embedding(E, 8)
    const int*   ei    = (const int*)d_in[4];     // edge_index    (2, E): [0]=dst, [1]=src
    const float* Wl10  = (const float*)d_in[5];
    const float* Wl11  = (const float*)d_in[6];
    const float* Wfc1  = (const float*)d_in[7];
    const float* Wfc2  = (const float*)d_in[8];
    const float* Wl20  = (const float*)d_in[9];
    const float* Wl21  = (const float*)d_in[10];
    const float* Wsc0  = (const float*)d_in[11];
    const float* Wsc1  = (const float*)d_in[12];
    float* out = (float*)d_out;

    int n = in_sizes[0] / 256;
    int E = in_sizes[2] / 4;

    zero_agg_kernel<<<(n * 128 + 255) / 256, 256>>>(n);
    node_pre_kernel<<<n, 64>>>(nf, Wl10, Wl11, n);
    edge_kernel<<<(E + 3) / 4, 256>>>(ea, ee, ei, Wfc1, Wfc2, E);
    node_post_kernel<<<n, 256>>>(nf, attrs, Wl20, Wl21, Wsc0, Wsc1, out, n);
}

// round 2
// speedup vs baseline: 1.9375x; 1.9375x over previous
#include <cuda_runtime.h>
#include <math.h>

#define MAXN 10000
#define MAXE 320000

// Scratch (__device__ globals per allocation-free rule)
__device__ float g_y[MAXN * 256];     // [node]: y0[64] | y1 m-major (64+m*64+v), scale 1/8 folded
__device__ float g_agg[MAXN * 512];   // reference concat layout, LIN2S (1/64) folded
__device__ float g_h[MAXE * 8];       // edge MLP hidden, INV_SQRT8 (2nd layer scale) folded
__device__ int   g_deg[MAXN];
__device__ int   g_row[MAXN + 1];
__device__ int   g_cursor[MAXN];
__device__ int   g_elist[MAXE];

#define INV_SQRT8 0.35355339059327373f
#define INV_SQRT3 0.5773502691896258f
#define LOG2F_C   0.6931471805599453f
#define LIN2S     0.015625f   // 1/(sqrt(32)*sqrt(128))
#define SCN       0.0625f     // 1/sqrt(64*4)

// ---------------------------------------------------------------------------
__global__ void zero_deg_kernel(int n) {
    int i = blockIdx.x * blockDim.x + threadIdx.x;
    if (i < n) g_deg[i] = 0;
}

__global__ void count_kernel(const int* __restrict__ eidx, int E) {
    int e = blockIdx.x * blockDim.x + threadIdx.x;
    if (e < E) atomicAdd(&g_deg[eidx[e]], 1);
}

// Single-block exclusive scan over g_deg -> g_row, g_cursor; g_row[n]=E.
__global__ void scan_kernel(int n) {
    __shared__ int part[1024];
    int tid = threadIdx.x;
    int IT = (n + 1023) >> 10;
    int base = tid * IT;
    int s = 0;
    for (int i = 0; i < IT; ++i) {
        int idx = base + i;
        if (idx < n) s += g_deg[idx];
    }
    part[tid] = s;
    __syncthreads();
    // Hillis-Steele inclusive scan
    for (int off = 1; off < 1024; off <<= 1) {
        int v = (tid >= off) ? part[tid - off] : 0;
        __syncthreads();
        part[tid] += v;
        __syncthreads();
    }
    int run = part[tid] - s;  // exclusive prefix for this thread's range
    for (int i = 0; i < IT; ++i) {
        int idx = base + i;
        if (idx < n) {
            g_row[idx] = run;
            g_cursor[idx] = run;
            run += g_deg[idx];
        }
    }
    if (tid == 1023) g_row[n] = part[1023];
}

__global__ void scatter_kernel(const int* __restrict__ eidx, int E) {
    int e = blockIdx.x * blockDim.x + threadIdx.x;
    if (e < E) {
        int dst = eidx[e];
        int pos = atomicAdd(&g_cursor[dst], 1);
        g_elist[pos] = e;
    }
}

// ---------------------------------------------------------------------------
// Edge MLP layer 1: h = (softplus(emb @ Wfc1 / sqrt(8)) - log2) * (1/sqrt(8))
__global__ void h_kernel(const float* __restrict__ eemb,
                         const float* __restrict__ Wfc1, int E) {
    __shared__ float sW1[64];
    int tid = threadIdx.x;
    if (tid < 64) sW1[tid] = Wfc1[tid];
    __syncthreads();
    int e = blockIdx.x * blockDim.x + tid;
    if (e >= E) return;
    float4 e0 = *(const float4*)(eemb + (size_t)e * 8);
    float4 e1 = *(const float4*)(eemb + (size_t)e * 8 + 4);
    float emb[8] = {e0.x, e0.y, e0.z, e0.w, e1.x, e1.y, e1.z, e1.w};
    float h[8];
    #pragma unroll
    for (int j = 0; j < 8; ++j) {
        float z = 0.f;
        #pragma unroll
        for (int k = 0; k < 8; ++k) z = fmaf(emb[k], sW1[k * 8 + j], z);
        z *= INV_SQRT8;
        float sp = (z > 20.f) ? z : log1pf(__expf(z));
        h[j] = (sp - LOG2F_C) * INV_SQRT8;
    }
    float* o = g_h + (size_t)e * 8;
    *(float4*)o       = make_float4(h[0], h[1], h[2], h[3]);
    *(float4*)(o + 4) = make_float4(h[4], h[5], h[6], h[7]);
}

// ---------------------------------------------------------------------------
// Node pre GEMMs, K=64. mode 0: y0 rows=n (W_lin1_0). mode 1: y1 rows=3n (W_lin1_1).
// Block: 32 rows x 64 cols, 256 threads, 8 rows/thread.
__global__ void pre_gemm_kernel(const float* __restrict__ nf,
                                const float* __restrict__ W,
                                int n, int mode) {
    __shared__ __align__(16) float sIn[32 * 64];
    __shared__ __align__(16) float sW[64 * 64];
    int tid = threadIdx.x;
    int v = tid & 63, rgrp = tid >> 6;
    int rows = mode ? 3 * n : n;
    int rbase = blockIdx.x * 32;

    for (int i = tid; i < 4096; i += 256) sW[i] = W[i];
    for (int i = tid; i < 2048; i += 256) {
        int row = i >> 6, k = i & 63;
        int rg = rbase + row;
        float val = 0.f;
        if (rg < rows) {
            if (mode == 0) val = nf[(size_t)rg * 256 + k];
            else {
                int node = rg / 3, m = rg % 3;
                val = nf[(size_t)node * 256 + 64 + k * 3 + m];
            }
        }
        sIn[i] = val;
    }
    __syncthreads();

    float acc[8] = {0.f, 0.f, 0.f, 0.f, 0.f, 0.f, 0.f, 0.f};
    for (int kk = 0; kk < 64; kk += 4) {
        float w0 = sW[(kk + 0) * 64 + v];
        float w1 = sW[(kk + 1) * 64 + v];
        float w2 = sW[(kk + 2) * 64 + v];
        float w3 = sW[(kk + 3) * 64 + v];
        #pragma unroll
        for (int r = 0; r < 8; ++r) {
            const float4 in4 = *(const float4*)(sIn + (rgrp * 8 + r) * 64 + kk);
            acc[r] = fmaf(in4.x, w0, fmaf(in4.y, w1, fmaf(in4.z, w2, fmaf(in4.w, w3, acc[r]))));
        }
    }
    #pragma unroll
    for (int r = 0; r < 8; ++r) {
        int rg = rbase + rgrp * 8 + r;
        if (rg >= rows) continue;
        float val = acc[r] * 0.125f;
        if (mode == 0) g_y[(size_t)rg * 256 + v] = val;
        else {
            int node = rg / 3, m = rg % 3;
            g_y[(size_t)node * 256 + 64 + m * 64 + v] = val;
        }
    }
}

// ---------------------------------------------------------------------------
// Aggregation: block per node, 4 groups x 64 threads, register accumulators. No atomics.
__global__ void agg_kernel(const float* __restrict__ eattr,
                           const int*   __restrict__ eidx,
                           const float* __restrict__ Wfc2,
                           int E, int n) {
    __shared__ __align__(16) float sW2t[256 * 8];  // [col][j]
    __shared__ float spart[4 * 512];
    int tid = threadIdx.x;
    for (int i = tid; i < 2048; i += 256) {
        int col = i >> 3, j = i & 7;
        sW2t[i] = Wfc2[j * 256 + col];
    }
    __syncthreads();

    int node = blockIdx.x;
    int u = tid & 63, grp = tid >> 6;
    int rs = g_row[node], re = g_row[node + 1];

    float a0 = 0.f, a1 = 0.f, a2 = 0.f, a3 = 0.f, a4 = 0.f, a5 = 0.f, a6 = 0.f, a7 = 0.f;

    const float* wa = sW2t + u * 8;
    const float* wb = sW2t + (64 + u) * 8;
    const float* wc = sW2t + (128 + u) * 8;
    const float* wd = sW2t + (192 + u) * 8;

    for (int i = rs + grp; i < re; i += 4) {
        int eid = g_elist[i];
        int src = eidx[E + eid];
        float4 sh = *(const float4*)(eattr + (size_t)eid * 4);
        float4 h0 = *(const float4*)(g_h + (size_t)eid * 8);
        float4 h1 = *(const float4*)(g_h + (size_t)eid * 8 + 4);

        const float* ysrc = g_y + (size_t)src * 256;
        float xs0 = ysrc[u];
        float x1x = ysrc[64 + u];
        float x1y = ysrc[128 + u];
        float x1z = ysrc[192 + u];

        float w1 = h0.x*wa[0] + h0.y*wa[1] + h0.z*wa[2] + h0.w*wa[3]
                 + h1.x*wa[4] + h1.y*wa[5] + h1.z*wa[6] + h1.w*wa[7];
        float w2 = h0.x*wb[0] + h0.y*wb[1] + h0.z*wb[2] + h0.w*wb[3]
                 + h1.x*wb[4] + h1.y*wb[5] + h1.z*wb[6] + h1.w*wb[7];
        float w3 = h0.x*wc[0] + h0.y*wc[1] + h0.z*wc[2] + h0.w*wc[3]
                 + h1.x*wc[4] + h1.y*wc[5] + h1.z*wc[6] + h1.w*wc[7];
        float w4 = h0.x*wd[0] + h0.y*wd[1] + h0.z*wd[2] + h0.w*wd[3]
                 + h1.x*wd[4] + h1.y*wd[5] + h1.z*wd[6] + h1.w*wd[7];

        float dotv = x1x * sh.y + x1y * sh.z + x1z * sh.w;
        float a2c = w2 * xs0;
        float a3c = w3 * sh.x;
        a0 = fmaf(w1 * xs0, sh.x, a0);
        a1 = fmaf(w4 * INV_SQRT3, dotv, a1);
        a2 = fmaf(a2c, sh.y, a2);
        a3 = fmaf(a2c, sh.z, a3);
        a4 = fmaf(a2c, sh.w, a4);
        a5 = fmaf(a3c, x1x, a5);
        a6 = fmaf(a3c, x1y, a6);
        a7 = fmaf(a3c, x1z, a7);
    }

    float* sp = spart + grp * 512;
    sp[u] = a0;
    sp[64 + u] = a1;
    sp[128 + 3 * u + 0] = a2;
    sp[128 + 3 * u + 1] = a3;
    sp[128 + 3 * u + 2] = a4;
    sp[320 + 3 * u + 0] = a5;
    sp[320 + 3 * u + 1] = a6;
    sp[320 + 3 * u + 2] = a7;
    __syncthreads();

    float* arow = g_agg + (size_t)node * 512;
    for (int idx = tid; idx < 512; idx += 256)
        arow[idx] = (spart[idx] + spart[512 + idx] + spart[1024 + idx] + spart[1536 + idx]) * LIN2S;
}

// ---------------------------------------------------------------------------
// Node post GEMM, K=384 (3 chunks of 128): [agg_part | attrs (x) x] @ [W_lin2 ; W_sc] + write out.
// mode 0: o0 rows=n. mode 1: o1 rows=3n (shared weights across m).
__global__ void post_gemm_kernel(const float* __restrict__ nf,
                                 const float* __restrict__ attrs,
                                 const float* __restrict__ Wlin,
                                 const float* __restrict__ Wsc,
                                 float* __restrict__ out,
                                 int n, int mode) {
    __shared__ __align__(16) float sIn[32 * 128];   // 16 KB
    __shared__ __align__(16) float sW[128 * 64];    // 32 KB
    int tid = threadIdx.x;
    int v = tid & 63, rgrp = tid >> 6;
    int rows = mode ? 3 * n : n;
    int rbase = blockIdx.x * 32;

    float acc[8] = {0.f, 0.f, 0.f, 0.f, 0.f, 0.f, 0.f, 0.f};

    for (int c = 0; c < 3; ++c) {
        // load weight chunk
        for (int i = tid; i < 8192; i += 256) {
            int kk = i >> 6, vv = i & 63;
            int k = c * 128 + kk;
            float w;
            if (k < 128) w = Wlin[k * 64 + vv];
            else {
                int t2 = k - 128, a = t2 >> 6, uu = t2 & 63;
                w = Wsc[uu * 256 + a * 64 + vv];
            }
            sW[i] = w;
        }
        // load input chunk
        for (int i = tid; i < 4096; i += 256) {
            int row = i >> 7, kk = i & 127;
            int rg = rbase + row;
            int k = c * 128 + kk;
            float val = 0.f;
            if (rg < rows) {
                if (mode == 0) {
                    if (k < 128) val = g_agg[(size_t)rg * 512 + k];
                    else {
                        int t2 = k - 128, a = t2 >> 6, uu = t2 & 63;
                        val = attrs[(size_t)rg * 4 + a] * nf[(size_t)rg * 256 + uu] * SCN;
                    }
                } else {
                    int node = rg / 3, m = rg % 3;
                    if (k < 128) val = g_agg[(size_t)node * 512 + 128 + k * 3 + m];
                    else {
                        int t2 = k - 128, a = t2 >> 6, uu = t2 & 63;
                        val = attrs[(size_t)node * 4 + a] * nf[(size_t)node * 256 + 64 + uu * 3 + m] * SCN;
                    }
                }
            }
            sIn[i] = val;
        }
        __syncthreads();

        for (int kk = 0; kk < 128; kk += 4) {
            float w0 = sW[(kk + 0) * 64 + v];
            float w1 = sW[(kk + 1) * 64 + v];
            float w2 = sW[(kk + 2) * 64 + v];
            float w3 = sW[(kk + 3) * 64 + v];
            #pragma unroll
            for (int r = 0; r < 8; ++r) {
                const float4 in4 = *(const float4*)(sIn + (rgrp * 8 + r) * 128 + kk);
                acc[r] = fmaf(in4.x, w0, fmaf(in4.y, w1, fmaf(in4.z, w2, fmaf(in4.w, w3, acc[r]))));
            }
        }
        __syncthreads();
    }

    #pragma unroll
    for (int r = 0; r < 8; ++r) {
        int rg = rbase + rgrp * 8 + r;
        if (rg >= rows) continue;
        if (mode == 0) out[(size_t)rg * 256 + v] = acc[r];
        else {
            int node = rg / 3, m = rg % 3;
            out[(size_t)node * 256 + 64 + v * 3 + m] = acc[r];
        }
    }
}

// ---------------------------------------------------------------------------
extern "C" void kernel_launch(void* const* d_in, const int* in_sizes, int n_in,
                              void* d_out, int out_size) {
    const float* nf    = (const float*)d_in[0];
    const float* attrs = (const float*)d_in[1];
    const float* ea    = (const float*)d_in[2];
    const float* ee    = (const float*)d_in[3];
    const int*   ei    = (const int*)d_in[4];
    const float* Wl10  = (const float*)d_in[5];
    const float* Wl11  = (const float*)d_in[6];
    const float* Wfc1  = (const float*)d_in[7];
    const float* Wfc2  = (const float*)d_in[8];
    const float* Wl20  = (const float*)d_in[9];
    const float* Wl21  = (const float*)d_in[10];
    const float* Wsc0  = (const float*)d_in[11];
    const float* Wsc1  = (const float*)d_in[12];
    float* out = (float*)d_out;

    int n = in_sizes[0] / 256;
    int E = in_sizes[2] / 4;

    // CSR build
    zero_deg_kernel<<<(n + 255) / 256, 256>>>(n);
    count_kernel<<<(E + 255) / 256, 256>>>(ei, E);
    scan_kernel<<<1, 1024>>>(n);
    scatter_kernel<<<(E + 255) / 256, 256>>>(ei, E);

    // Edge MLP hidden layer
    h_kernel<<<(E + 255) / 256, 256>>>(ee, Wfc1, E);

    // Node pre (y0, y1)
    pre_gemm_kernel<<<(n + 31) / 32, 256>>>(nf, Wl10, n, 0);
    pre_gemm_kernel<<<(3 * n + 31) / 32, 256>>>(nf, Wl11, n, 1);

    // Aggregation (no atomics)
    agg_kernel<<<n, 256>>>(ea, ei, Wfc2, E, n);

    // Node post (o0, o1)
    post_gemm_kernel<<<(n + 31) / 32, 256>>>(nf, attrs, Wl20, Wsc0, out, n, 0);
    post_gemm_kernel<<<(3 * n + 31) / 32, 256>>>(nf, attrs, Wl21, Wsc1, out, n, 1);
}

// round 3
// speedup vs baseline: 2.2902x; 1.1820x over previous
#include <cuda_runtime.h>
#include <math.h>

#define MAXN 10000
#define MAXE 320000

// Scratch (__device__ globals per allocation-free rule)
__device__ float g_y[MAXN * 256];     // [node]: y0[64] | y1 m-major (64+m*64+v), scale 1/8 folded
__device__ float g_agg[MAXN * 512];   // reference concat layout, LIN2S (1/64) folded
__device__ float g_h[MAXE * 8];       // edge MLP hidden, INV_SQRT8 (2nd layer scale) folded
__device__ int   g_deg[MAXN];
__device__ int   g_row[MAXN + 1];
__device__ int   g_cursor[MAXN];
__device__ int   g_elist[MAXE];

#define INV_SQRT8 0.35355339059327373f
#define INV_SQRT3 0.5773502691896258f
#define LOG2F_C   0.6931471805599453f
#define LIN2S     0.015625f   // 1/(sqrt(32)*sqrt(128))
#define SCN       0.0625f     // 1/sqrt(64*4)

// ---------------------------------------------------------------------------
__global__ void zero_deg_kernel(int n) {
    int i = blockIdx.x * blockDim.x + threadIdx.x;
    if (i < n) g_deg[i] = 0;
}

__global__ void count_kernel(const int* __restrict__ eidx, int E) {
    int e = blockIdx.x * blockDim.x + threadIdx.x;
    if (e < E) atomicAdd(&g_deg[eidx[e]], 1);
}

// Single-block exclusive scan over g_deg -> g_row, g_cursor; g_row[n]=E.
__global__ void scan_kernel(int n) {
    __shared__ int part[1024];
    int tid = threadIdx.x;
    int IT = (n + 1023) >> 10;
    int base = tid * IT;
    int s = 0;
    for (int i = 0; i < IT; ++i) {
        int idx = base + i;
        if (idx < n) s += g_deg[idx];
    }
    part[tid] = s;
    __syncthreads();
    for (int off = 1; off < 1024; off <<= 1) {
        int v = (tid >= off) ? part[tid - off] : 0;
        __syncthreads();
        part[tid] += v;
        __syncthreads();
    }
    int run = part[tid] - s;
    for (int i = 0; i < IT; ++i) {
        int idx = base + i;
        if (idx < n) {
            g_row[idx] = run;
            g_cursor[idx] = run;
            run += g_deg[idx];
        }
    }
    if (tid == 1023) g_row[n] = part[1023];
}

__global__ void scatter_kernel(const int* __restrict__ eidx, int E) {
    int e = blockIdx.x * blockDim.x + threadIdx.x;
    if (e < E) {
        int dst = eidx[e];
        int pos = atomicAdd(&g_cursor[dst], 1);
        g_elist[pos] = e;
    }
}

// ---------------------------------------------------------------------------
// Edge MLP layer 1: h = (softplus(emb @ Wfc1 / sqrt(8)) - log2) * (1/sqrt(8))
__global__ void h_kernel(const float* __restrict__ eemb,
                         const float* __restrict__ Wfc1, int E) {
    __shared__ float sW1[64];
    int tid = threadIdx.x;
    if (tid < 64) sW1[tid] = Wfc1[tid];
    __syncthreads();
    int e = blockIdx.x * blockDim.x + tid;
    if (e >= E) return;
    float4 e0 = *(const float4*)(eemb + (size_t)e * 8);
    float4 e1 = *(const float4*)(eemb + (size_t)e * 8 + 4);
    float emb[8] = {e0.x, e0.y, e0.z, e0.w, e1.x, e1.y, e1.z, e1.w};
    float h[8];
    #pragma unroll
    for (int j = 0; j < 8; ++j) {
        float z = 0.f;
        #pragma unroll
        for (int k = 0; k < 8; ++k) z = fmaf(emb[k], sW1[k * 8 + j], z);
        z *= INV_SQRT8;
        float sp = (z > 20.f) ? z : log1pf(__expf(z));
        h[j] = (sp - LOG2F_C) * INV_SQRT8;
    }
    float* o = g_h + (size_t)e * 8;
    *(float4*)o       = make_float4(h[0], h[1], h[2], h[3]);
    *(float4*)(o + 4) = make_float4(h[4], h[5], h[6], h[7]);
}

// ---------------------------------------------------------------------------
// Node pre GEMMs, K=64 (both modes in one launch).
// Blocks [0, nb0): y0 rows=n with Wl10. Blocks [nb0, nb0+nb1): y1 rows=3n with Wl11.
__global__ void pre_gemm_kernel(const float* __restrict__ nf,
                                const float* __restrict__ Wl10,
                                const float* __restrict__ Wl11,
                                int n, int nb0) {
    __shared__ __align__(16) float sIn[32 * 64];
    __shared__ __align__(16) float sW[64 * 64];
    int tid = threadIdx.x;
    int v = tid & 63, rgrp = tid >> 6;
    int mode = (blockIdx.x >= nb0) ? 1 : 0;
    int blk = mode ? (blockIdx.x - nb0) : blockIdx.x;
    int rows = mode ? 3 * n : n;
    int rbase = blk * 32;
    const float* W = mode ? Wl11 : Wl10;

    for (int i = tid; i < 4096; i += 256) sW[i] = W[i];
    for (int i = tid; i < 2048; i += 256) {
        int row = i >> 6, k = i & 63;
        int rg = rbase + row;
        float val = 0.f;
        if (rg < rows) {
            if (mode == 0) val = nf[(size_t)rg * 256 + k];
            else {
                int node = rg / 3, m = rg % 3;
                val = nf[(size_t)node * 256 + 64 + k * 3 + m];
            }
        }
        sIn[i] = val;
    }
    __syncthreads();

    float acc[8] = {0.f, 0.f, 0.f, 0.f, 0.f, 0.f, 0.f, 0.f};
    for (int kk = 0; kk < 64; kk += 4) {
        float w0 = sW[(kk + 0) * 64 + v];
        float w1 = sW[(kk + 1) * 64 + v];
        float w2 = sW[(kk + 2) * 64 + v];
        float w3 = sW[(kk + 3) * 64 + v];
        #pragma unroll
        for (int r = 0; r < 8; ++r) {
            const float4 in4 = *(const float4*)(sIn + (rgrp * 8 + r) * 64 + kk);
            acc[r] = fmaf(in4.x, w0, fmaf(in4.y, w1, fmaf(in4.z, w2, fmaf(in4.w, w3, acc[r]))));
        }
    }
    #pragma unroll
    for (int r = 0; r < 8; ++r) {
        int rg = rbase + rgrp * 8 + r;
        if (rg >= rows) continue;
        float val = acc[r] * 0.125f;
        if (mode == 0) g_y[(size_t)rg * 256 + v] = val;
        else {
            int node = rg / 3, m = rg % 3;
            g_y[(size_t)node * 256 + 64 + m * 64 + v] = val;
        }
    }
}

// ---------------------------------------------------------------------------
// Aggregation: block per node, 4 groups x 64 threads, register accumulators,
// W_fc2 columns held in REGISTERS (loop-invariant per thread). No atomics, no LDS in loop.
__global__ void __launch_bounds__(256) agg_kernel(const float* __restrict__ eattr,
                           const int*   __restrict__ eidx,
                           const float* __restrict__ Wfc2,
                           int E, int n) {
    __shared__ float spart[4 * 512];
    int tid = threadIdx.x;
    int u = tid & 63, grp = tid >> 6;

    // Per-thread weight columns u, 64+u, 128+u, 192+u for j=0..7 (coalesced loads, once).
    float wA[8], wB[8], wC[8], wD[8];
    #pragma unroll
    for (int j = 0; j < 8; ++j) {
        const float* r = Wfc2 + j * 256;
        wA[j] = __ldg(r + u);
        wB[j] = __ldg(r + 64 + u);
        wC[j] = __ldg(r + 128 + u);
        wD[j] = __ldg(r + 192 + u);
    }

    int node = blockIdx.x;
    int rs = g_row[node], re = g_row[node + 1];

    float a0 = 0.f, a1 = 0.f, a2 = 0.f, a3 = 0.f, a4 = 0.f, a5 = 0.f, a6 = 0.f, a7 = 0.f;

    for (int i = rs + grp; i < re; i += 4) {
        int eid = __ldg(g_elist + i);
        int src = __ldg(eidx + E + eid);
        float4 sh = __ldg((const float4*)(eattr + (size_t)eid * 4));
        float4 h0 = __ldg((const float4*)(g_h + (size_t)eid * 8));
        float4 h1 = __ldg((const float4*)(g_h + (size_t)eid * 8 + 4));

        const float* ysrc = g_y + (size_t)src * 256;
        float xs0 = __ldg(ysrc + u);
        float x1x = __ldg(ysrc + 64 + u);
        float x1y = __ldg(ysrc + 128 + u);
        float x1z = __ldg(ysrc + 192 + u);

        float w1 = fmaf(h0.x, wA[0], fmaf(h0.y, wA[1], fmaf(h0.z, wA[2], fmaf(h0.w, wA[3],
                   fmaf(h1.x, wA[4], fmaf(h1.y, wA[5], fmaf(h1.z, wA[6], h1.w * wA[7])))))));
        float w2 = fmaf(h0.x, wB[0], fmaf(h0.y, wB[1], fmaf(h0.z, wB[2], fmaf(h0.w, wB[3],
                   fmaf(h1.x, wB[4], fmaf(h1.y, wB[5], fmaf(h1.z, wB[6], h1.w * wB[7])))))));
        float w3 = fmaf(h0.x, wC[0], fmaf(h0.y, wC[1], fmaf(h0.z, wC[2], fmaf(h0.w, wC[3],
                   fmaf(h1.x, wC[4], fmaf(h1.y, wC[5], fmaf(h1.z, wC[6], h1.w * wC[7])))))));
        float w4 = fmaf(h0.x, wD[0], fmaf(h0.y, wD[1], fmaf(h0.z, wD[2], fmaf(h0.w, wD[3],
                   fmaf(h1.x, wD[4], fmaf(h1.y, wD[5], fmaf(h1.z, wD[6], h1.w * wD[7])))))));

        float dotv = fmaf(x1x, sh.y, fmaf(x1y, sh.z, x1z * sh.w));
        float a2c = w2 * xs0;
        float a3c = w3 * sh.x;
        a0 = fmaf(w1 * xs0, sh.x, a0);
        a1 = fmaf(w4 * INV_SQRT3, dotv, a1);
        a2 = fmaf(a2c, sh.y, a2);
        a3 = fmaf(a2c, sh.z, a3);
        a4 = fmaf(a2c, sh.w, a4);
        a5 = fmaf(a3c, x1x, a5);
        a6 = fmaf(a3c, x1y, a6);
        a7 = fmaf(a3c, x1z, a7);
    }

    float* sp = spart + grp * 512;
    sp[u] = a0;
    sp[64 + u] = a1;
    sp[128 + 3 * u + 0] = a2;
    sp[128 + 3 * u + 1] = a3;
    sp[128 + 3 * u + 2] = a4;
    sp[320 + 3 * u + 0] = a5;
    sp[320 + 3 * u + 1] = a6;
    sp[320 + 3 * u + 2] = a7;
    __syncthreads();

    float* arow = g_agg + (size_t)node * 512;
    for (int idx = tid; idx < 512; idx += 256)
        arow[idx] = (spart[idx] + spart[512 + idx] + spart[1024 + idx] + spart[1536 + idx]) * LIN2S;
}

// ---------------------------------------------------------------------------
// Node post GEMM, K=384 (3 chunks of 128): [agg_part | attrs (x) x] @ [W_lin2 ; W_sc].
// Both modes in one launch: blocks [0,nb0) = o0 (n rows); [nb0, nb0+nb1) = o1 (3n rows).
__global__ void post_gemm_kernel(const float* __restrict__ nf,
                                 const float* __restrict__ attrs,
                                 const float* __restrict__ Wl20,
                                 const float* __restrict__ Wl21,
                                 const float* __restrict__ Wsc0,
                                 const float* __restrict__ Wsc1,
                                 float* __restrict__ out,
                                 int n, int nb0) {
    __shared__ __align__(16) float sIn[32 * 128];   // 16 KB
    __shared__ __align__(16) float sW[128 * 64];    // 32 KB
    int tid = threadIdx.x;
    int v = tid & 63, rgrp = tid >> 6;
    int mode = (blockIdx.x >= nb0) ? 1 : 0;
    int blk = mode ? (blockIdx.x - nb0) : blockIdx.x;
    int rows = mode ? 3 * n : n;
    int rbase = blk * 32;
    const float* Wlin = mode ? Wl21 : Wl20;
    const float* Wsc  = mode ? Wsc1 : Wsc0;

    float acc[8] = {0.f, 0.f, 0.f, 0.f, 0.f, 0.f, 0.f, 0.f};

    for (int c = 0; c < 3; ++c) {
        for (int i = tid; i < 8192; i += 256) {
            int kk = i >> 6, vv = i & 63;
            int k = c * 128 + kk;
            float w;
            if (k < 128) w = Wlin[k * 64 + vv];
            else {
                int t2 = k - 128, a = t2 >> 6, uu = t2 & 63;
                w = Wsc[uu * 256 + a * 64 + vv];
            }
            sW[i] = w;
        }
        for (int i = tid; i < 4096; i += 256) {
            int row = i >> 7, kk = i & 127;
            int rg = rbase + row;
            int k = c * 128 + kk;
            float val = 0.f;
            if (rg < rows) {
                if (mode == 0) {
                    if (k < 128) val = g_agg[(size_t)rg * 512 + k];
                    else {
                        int t2 = k - 128, a = t2 >> 6, uu = t2 & 63;
                        val = attrs[(size_t)rg * 4 + a] * nf[(size_t)rg * 256 + uu] * SCN;
                    }
                } else {
                    int node = rg / 3, m = rg % 3;
                    if (k < 128) val = g_agg[(size_t)node * 512 + 128 + k * 3 + m];
                    else {
                        int t2 = k - 128, a = t2 >> 6, uu = t2 & 63;
                        val = attrs[(size_t)node * 4 + a] * nf[(size_t)node * 256 + 64 + uu * 3 + m] * SCN;
                    }
                }
            }
            sIn[i] = val;
        }
        __syncthreads();

        for (int kk = 0; kk < 128; kk += 4) {
            float w0 = sW[(kk + 0) * 64 + v];
            float w1 = sW[(kk + 1) * 64 + v];
            float w2 = sW[(kk + 2) * 64 + v];
            float w3 = sW[(kk + 3) * 64 + v];
            #pragma unroll
            for (int r = 0; r < 8; ++r) {
                const float4 in4 = *(const float4*)(sIn + (rgrp * 8 + r) * 128 + kk);
                acc[r] = fmaf(in4.x, w0, fmaf(in4.y, w1, fmaf(in4.z, w2, fmaf(in4.w, w3, acc[r]))));
            }
        }
        __syncthreads();
    }

    #pragma unroll
    for (int r = 0; r < 8; ++r) {
        int rg = rbase + rgrp * 8 + r;
        if (rg >= rows) continue;
        if (mode == 0) out[(size_t)rg * 256 + v] = acc[r];
        else {
            int node = rg / 3, m = rg % 3;
            out[(size_t)node * 256 + 64 + v * 3 + m] = acc[r];
        }
    }
}

// ---------------------------------------------------------------------------
extern "C" void kernel_launch(void* const* d_in, const int* in_sizes, int n_in,
                              void* d_out, int out_size) {
    const float* nf    = (const float*)d_in[0];
    const float* attrs = (const float*)d_in[1];
    const float* ea    = (const float*)d_in[2];
    const float* ee    = (const float*)d_in[3];
    const int*   ei    = (const int*)d_in[4];
    const float* Wl10  = (const float*)d_in[5];
    const float* Wl11  = (const float*)d_in[6];
    const float* Wfc1  = (const float*)d_in[7];
    const float* Wfc2  = (const float*)d_in[8];
    const float* Wl20  = (const float*)d_in[9];
    const float* Wl21  = (const float*)d_in[10];
    const float* Wsc0  = (const float*)d_in[11];
    const float* Wsc1  = (const float*)d_in[12];
    float* out = (float*)d_out;

    int n = in_sizes[0] / 256;
    int E = in_sizes[2] / 4;

    // CSR build
    zero_deg_kernel<<<(n + 255) / 256, 256>>>(n);
    count_kernel<<<(E + 255) / 256, 256>>>(ei, E);
    scan_kernel<<<1, 1024>>>(n);
    scatter_kernel<<<(E + 255) / 256, 256>>>(ei, E);

    // Edge MLP hidden layer
    h_kernel<<<(E + 255) / 256, 256>>>(ee, Wfc1, E);

    // Node pre (y0, y1) fused
    int pre_nb0 = (n + 31) / 32, pre_nb1 = (3 * n + 31) / 32;
    pre_gemm_kernel<<<pre_nb0 + pre_nb1, 256>>>(nf, Wl10, Wl11, n, pre_nb0);

    // Aggregation (no atomics, register weights)
    agg_kernel<<<n, 256>>>(ea, ei, Wfc2, E, n);

    // Node post (o0, o1) fused
    int post_nb0 = (n + 31) / 32, post_nb1 = (3 * n + 31) / 32;
    post_gemm_kernel<<<post_nb0 + post_nb1, 256>>>(nf, attrs, Wl20, Wl21, Wsc0, Wsc1, out, n, post_nb0);
}